// round 17
// baseline (speedup 1.0000x reference)
#include <cuda_runtime.h>

// AdderConv + BatchNorm2d (training stats): x[8,32,28,28], W[64,32,3,3], pad=1.
// out[n,o,h,w] = -sum_k |x - w|, then per-channel BN (biased var, eps=1e-5).
//
// SINGLE fused kernel: grid (4 spatial 14x14 tiles, 8 oc-groups, 8 n) = 256
// blocks x 256 thr, 41KB smem, all co-resident (2/SM).
// R16 found the binder: the 2x LDS.128 weight broadcasts per k-iter (~4 cyc
// each on the smem port). R17 amortizes them over a VERTICAL PIXEL PAIR
// (rows ph, ph+7) per thread, with an in-block channel-team split to keep all
// 8 warps busy: teamA (warps 0-3, 98 active) ch 0-15, teamB (warps 4-7) ch
// 16-31. Per (c,r,q): 2 LDS.32 + 2 LDS.128 feed 16 elem-ops (was 8 ops for
// 1 LDS.32 + 2 LDS.128). Scalar acc += fabsf(x + nw) -> 2 FADD (|src| mod).
// Teams combine via smem; block stats; replay-safe ticket barrier; per-channel
// scale/bias; in-register normalize; single write.

__device__ float g_psum[64 * 32];     // [oc][pidx], pidx = n*4 + s
__device__ float g_psumsq[64 * 32];
__device__ unsigned g_ctr;            // monotonic ticket counter (never reset)

__global__ __launch_bounds__(256) void fused_kernel(
    const float* __restrict__ x, const float* __restrict__ W,
    const float* __restrict__ gamma, const float* __restrict__ beta,
    float* __restrict__ out)
{
    __shared__ __align__(16) float xs[32 * 16 * 16];   // 32KB; reused for combine
    __shared__ __align__(16) float nws[288 * 8];       // 9KB negated w, k-major
    __shared__ float red[16][4];                       // teamA warp partials
    __shared__ float2 scb[8];                          // per-oc {scale, bias}

    const int s   = blockIdx.x;   // spatial tile 0..3
    const int ocg = blockIdx.y;   // 0..7 (8 output channels each)
    const int n   = blockIdx.z;   // 0..7
    const int th  = (s >> 1) * 14;
    const int tw  = (s & 1) * 14;
    const int tid = threadIdx.x;
    const int wid = tid >> 5;     // 0..7
    const int lid = tid & 31;
    const int team = tid >> 7;    // 0: ch 0-15, 1: ch 16-31
    const int p    = tid & 127;   // slot in team; active if < 98
    const bool act = (p < 98);
    const int ph = p / 14;        // 0..6 (garbage for inactive, unused)
    const int pw = p - ph * 14;   // 0..13

    // ---- prologue: x tile (zero halo) + negated weights ----
    const float* xb = x + n * (32 * 28 * 28);
    #pragma unroll
    for (int i = tid; i < 32 * 256; i += 256) {
        int c = i >> 8, cell = i & 255;
        int r = cell >> 4, col = cell & 15;
        int gh = th - 1 + r, gw = tw - 1 + col;
        float v = 0.f;
        if ((unsigned)gh < 28u && (unsigned)gw < 28u)
            v = xb[c * 784 + gh * 28 + gw];
        xs[i] = v;
    }
    const float* Wb = W + ocg * (8 * 288);
    #pragma unroll
    for (int i = tid; i < 8 * 288; i += 256) {
        int o = i & 7, k = i >> 3;
        nws[k * 8 + o] = -Wb[o * 288 + k];
    }
    __syncthreads();

    // ---- mainloop: vertical pixel pair (ph, ph+7) x 8 ocs, 16 channels ----
    float a0[8] = {0.f, 0.f, 0.f, 0.f, 0.f, 0.f, 0.f, 0.f};   // row ph
    float a1[8] = {0.f, 0.f, 0.f, 0.f, 0.f, 0.f, 0.f, 0.f};   // row ph+7
    if (act) {
        const float* xp = xs + (team * 16) * 256 + ph * 16 + pw;
        const float4* wk = (const float4*)(nws + (team * 16) * 72);

        #pragma unroll 1
        for (int c = 0; c < 16; ++c) {
            const float* xc = xp + c * 256;
            const float4* wc = wk + c * 18;
            #pragma unroll
            for (int r = 0; r < 3; ++r) {
                #pragma unroll
                for (int q = 0; q < 3; ++q) {
                    float xv0 = xc[r * 16 + q];
                    float xv1 = xc[(r + 7) * 16 + q];
                    float4 wa = wc[(r * 3 + q) * 2];
                    float4 wb = wc[(r * 3 + q) * 2 + 1];
                    a0[0] += fabsf(xv0 + wa.x);  a1[0] += fabsf(xv1 + wa.x);
                    a0[1] += fabsf(xv0 + wa.y);  a1[1] += fabsf(xv1 + wa.y);
                    a0[2] += fabsf(xv0 + wa.z);  a1[2] += fabsf(xv1 + wa.z);
                    a0[3] += fabsf(xv0 + wa.w);  a1[3] += fabsf(xv1 + wa.w);
                    a0[4] += fabsf(xv0 + wb.x);  a1[4] += fabsf(xv1 + wb.x);
                    a0[5] += fabsf(xv0 + wb.y);  a1[5] += fabsf(xv1 + wb.y);
                    a0[6] += fabsf(xv0 + wb.z);  a1[6] += fabsf(xv1 + wb.z);
                    a0[7] += fabsf(xv0 + wb.w);  a1[7] += fabsf(xv1 + wb.w);
                }
            }
        }
    }

    // ---- team combine via smem (xs is free now) ----
    float* comb = xs;                  // 98 slots x 16 floats = 6.3KB
    __syncthreads();
    if (team == 1 && act) {
        float4* dst = (float4*)(comb + p * 16);
        dst[0] = make_float4(a0[0], a0[1], a0[2], a0[3]);
        dst[1] = make_float4(a0[4], a0[5], a0[6], a0[7]);
        dst[2] = make_float4(a1[0], a1[1], a1[2], a1[3]);
        dst[3] = make_float4(a1[4], a1[5], a1[6], a1[7]);
    }
    __syncthreads();
    if (team == 0 && act) {
        const float4* src = (const float4*)(comb + p * 16);
        float4 b0 = src[0], b1 = src[1], b2 = src[2], b3 = src[3];
        a0[0] += b0.x; a0[1] += b0.y; a0[2] += b0.z; a0[3] += b0.w;
        a0[4] += b1.x; a0[5] += b1.y; a0[6] += b1.z; a0[7] += b1.w;
        a1[0] += b2.x; a1[1] += b2.y; a1[2] += b2.z; a1[3] += b2.w;
        a1[4] += b3.x; a1[5] += b3.y; a1[6] += b3.z; a1[7] += b3.w;
    }

    // ---- block stats (teamA): warp reduce 16 values, fold 4 warps ----
    {
        const bool use = (team == 0) && act;
        float sv[8], qv[8];
        #pragma unroll
        for (int j = 0; j < 8; ++j) {
            float v0 = use ? a0[j] : 0.f;
            float v1 = use ? a1[j] : 0.f;
            sv[j] = -(v0 + v1);        // out values are -a
            qv[j] = v0 * v0 + v1 * v1;
        }
        #pragma unroll
        for (int d = 16; d > 0; d >>= 1) {
            #pragma unroll
            for (int j = 0; j < 8; ++j) {
                sv[j] += __shfl_down_sync(0xFFFFFFFFu, sv[j], d);
                qv[j] += __shfl_down_sync(0xFFFFFFFFu, qv[j], d);
            }
        }
        if (team == 0 && lid == 0) {
            #pragma unroll
            for (int j = 0; j < 8; ++j) {
                red[j][wid]     = sv[j];
                red[j + 8][wid] = qv[j];
            }
        }
    }
    __syncthreads();

    const int pidx = n * 4 + s;
    if (tid < 16) {
        float t = red[tid][0] + red[tid][1] + red[tid][2] + red[tid][3];
        if (tid < 8) g_psum[(ocg * 8 + tid) * 32 + pidx] = t;
        else         g_psumsq[(ocg * 8 + (tid - 8)) * 32 + pidx] = t;
    }
    __syncthreads();

    // ---- replay-safe ticket barrier over the 256 co-resident blocks ----
    if (tid == 0) {
        __threadfence();
        unsigned arrival = atomicAdd(&g_ctr, 1u);
        unsigned target = ((arrival >> 8) + 1u) << 8;   // this launch's 256th ticket
        while ((int)(*(volatile unsigned*)&g_ctr - target) < 0) __nanosleep(64);
        __threadfence();
    }
    __syncthreads();

    // ---- per-channel stats: warp w folds oc (ocg*8+w)'s 32 partials ----
    {
        const int oc = ocg * 8 + wid;
        float ss = *(volatile float*)&g_psum[oc * 32 + lid];
        float qq = *(volatile float*)&g_psumsq[oc * 32 + lid];
        #pragma unroll
        for (int d = 16; d > 0; d >>= 1) {
            ss += __shfl_down_sync(0xFFFFFFFFu, ss, d);
            qq += __shfl_down_sync(0xFFFFFFFFu, qq, d);
        }
        if (lid == 0) {
            float mean = ss * (1.f / 6272.f);
            float var  = qq * (1.f / 6272.f) - mean * mean;
            float sc = gamma[oc] * rsqrtf(var + 1e-5f);
            scb[wid] = make_float2(sc, beta[oc] - mean * sc);
        }
    }
    __syncthreads();

    // ---- normalize in registers (teamA), single global write ----
    if (team == 0 && act) {
        const int gh0 = th + ph, gw = tw + pw;
        float* ob = out + (n * 64 + ocg * 8) * 784 + gh0 * 28 + gw;
        #pragma unroll
        for (int j = 0; j < 8; ++j) {
            float2 c = scb[j];
            ob[j * 784]           = fmaf(a0[j], -c.x, c.y);   // row ph
            ob[j * 784 + 7 * 28]  = fmaf(a1[j], -c.x, c.y);   // row ph+7
        }
    }
}

extern "C" void kernel_launch(void* const* d_in, const int* in_sizes, int n_in,
                              void* d_out, int out_size) {
    const float* x     = (const float*)d_in[0];  // [8,32,28,28]
    const float* W     = (const float*)d_in[1];  // [64,32,3,3]
    const float* gamma = (const float*)d_in[2];  // [64]
    const float* beta  = (const float*)d_in[3];  // [64]
    float* out = (float*)d_out;                  // [8,64,28,28]

    dim3 g1(4, 8, 8);
    fused_kernel<<<g1, 256>>>(x, W, gamma, beta, out);
}